// round 16
// baseline (speedup 1.0000x reference)
#include <cuda_runtime.h>
#include <cstdint>

// ---------------------------------------------------------------------------
// DirectedEdgeEncoder: out[E,128] = relu(concat(x[row[e]], edge_attr[e]) @ W^T + b)
// Split: U = x @ W1^T + b  (N=50k rows, tiny GEMM, L2-resident scratch)
//        out[e] = relu(ea[e] @ W2^T + U[row[e]])   (K=64 GEMM + cp.async gather)
// mma.sync m16n8k16 bf16, fp32 accum, 3-term hi/lo split (drops lo*lo, ~1e-5).
// Kernel2: NT=256, 2m x 4n warps (64x32 tiles), W2 fragments held in REGISTERS
// across all tiles (zero B-side LDSM), U gathered via cp.async overlapped with
// the MMA phase, coalesced smem-staged epilogue.
// ---------------------------------------------------------------------------

#define NT1 512
#define NT2 256
#define LDA_B 144                 // bytes per bf16 tile row (64 bf16 = 128B + 16 pad)
#define TILE_B (128 * LDA_B)      // 18432 B per operand tile (128 rows x 64 k)
#define LDA_OUT 136               // fp32 acc staging pitch (floats)

// kernel-2 smem: A (hi+lo, single buffer; W staged here during init) +
//                fp32 acc staging + U staging
#define K2_ACC  (2 * TILE_B)                     // 36864
#define K2_UST  (K2_ACC + 128 * LDA_OUT * 4)     // 36864 + 69632 = 106496
#define K2_SMEM (K2_UST + 128 * 512)             // + 65536 = 172032 B
// kernel-1 smem: single A (hi+lo) + W1 (hi+lo)
#define K1_AHI 0
#define K1_WHI (2 * TILE_B)
#define K1_SMEM (4 * TILE_B)      // 73728 B

#define U_MAX_ROWS 65536
__device__ float U_buf[(size_t)U_MAX_ROWS * 128];

static __device__ __forceinline__ uint32_t smem_u32(const void* p) {
    uint32_t a;
    asm("{ .reg .u64 t; cvta.to.shared.u64 t, %1; cvt.u32.u64 %0, t; }"
        : "=r"(a) : "l"(p));
    return a;
}

// pack two f32 -> bf16x2 (RN): 'e' low half (even k), 'o' high half (odd k)
static __device__ __forceinline__ uint32_t pack_bf16x2(float e, float o) {
    uint32_t r;
    asm("cvt.rn.bf16x2.f32 %0, %1, %2;" : "=r"(r) : "f"(o), "f"(e));
    return r;
}

// split (e,o) into bf16 hi word + bf16 lo (residual) word
static __device__ __forceinline__ void cvt2(float e, float o,
                                            uint32_t& hw, uint32_t& lw) {
    hw = pack_bf16x2(e, o);
    float fe = __uint_as_float(hw << 16);
    float fo = __uint_as_float(hw & 0xFFFF0000u);
    lw = pack_bf16x2(e - fe, o - fo);
}

#define LDSM4(r, addr)                                                        \
    asm volatile("ldmatrix.sync.aligned.m8n8.x4.shared.b16 {%0,%1,%2,%3}, [%4];" \
                 : "=r"((r)[0]), "=r"((r)[1]), "=r"((r)[2]), "=r"((r)[3])     \
                 : "r"(addr))

#define MMA_BF16(d, a, b0, b1)                                                \
    asm volatile("mma.sync.aligned.m16n8k16.row.col.f32.bf16.bf16.f32 "       \
                 "{%0,%1,%2,%3}, {%4,%5,%6,%7}, {%8,%9}, {%0,%1,%2,%3};"      \
                 : "+f"((d)[0]), "+f"((d)[1]), "+f"((d)[2]), "+f"((d)[3])     \
                 : "r"((a)[0]), "r"((a)[1]), "r"((a)[2]), "r"((a)[3]),        \
                   "r"(b0), "r"(b1))

#define CP_ASYNC16(dst, src)                                                  \
    asm volatile("cp.async.cg.shared.global [%0], [%1], 16;"                  \
                 :: "r"(dst), "l"(src) : "memory")

// convert 2 float4 (8 consecutive k-values of one row) -> bf16 hi/lo in SMEM
static __device__ __forceinline__ void store_row8(char* smem, int hi_off,
                                                  int r, int k0,
                                                  float4 a, float4 b) {
    uint32_t h[4], l[4];
    cvt2(a.x, a.y, h[0], l[0]);
    cvt2(a.z, a.w, h[1], l[1]);
    cvt2(b.x, b.y, h[2], l[2]);
    cvt2(b.z, b.w, h[3], l[3]);
    int off = r * LDA_B + (k0 << 1);
    *(uint4*)(smem + hi_off + off) = make_uint4(h[0], h[1], h[2], h[3]);
    *(uint4*)(smem + hi_off + TILE_B + off) = make_uint4(l[0], l[1], l[2], l[3]);
}

// NT1-wide: stage a [128 x 64] fp32 W slice (row stride 128 fl) as bf16 hi/lo
static __device__ __forceinline__ void stage_w_512(char* smem, int hi_off,
                                                   const float* __restrict__ Wsl,
                                                   int tid) {
    const int g = tid & 7, k0 = g << 3;
    const int r0 = tid >> 3;           // 0..63
    #pragma unroll
    for (int i = 0; i < 2; ++i) {
        int r = r0 + (i << 6);
        const float4* s = (const float4*)(Wsl + r * 128 + k0);
        store_row8(smem, hi_off, r, k0, s[0], s[1]);
    }
}

// ---------------------------------------------------------------------------
// Kernel 1: U[n, :] = x[n, :] @ W1^T + b     (no relu), n in [0, N)
// ---------------------------------------------------------------------------
__global__ void __launch_bounds__(NT1, 1)
build_u_kernel(const float* __restrict__ x,
               const float* __restrict__ W,
               const float* __restrict__ bias,
               int N)
{
    extern __shared__ __align__(1024) char smem[];
    const int tid  = threadIdx.x;
    const int lane = tid & 31;
    const int wid  = tid >> 5;
    const uint32_t sb = smem_u32(smem);
    const int n0 = blockIdx.x << 7;

    stage_w_512(smem, K1_WHI, W, tid);   // W1 = W[:, 0:64]

    // A tile: x rows n0..n0+127 (K = 64)
    {
        const int g = tid & 7, k0 = g << 3;
        const int r0 = tid >> 3;
        #pragma unroll
        for (int i = 0; i < 2; ++i) {
            int r = r0 + (i << 6);
            float4 a, b;
            if (n0 + r < N) {
                const float4* s = (const float4*)(x + ((size_t)(n0 + r) << 6) + k0);
                a = s[0]; b = s[1];
            } else {
                a = make_float4(0.f, 0.f, 0.f, 0.f); b = a;
            }
            store_row8(smem, K1_AHI, r, k0, a, b);
        }
    }
    __syncthreads();

    const int wm = wid & 3;
    const int wn = wid >> 2;
    const uint32_t a_off = (uint32_t)((lane & 15) * LDA_B + ((lane >> 4) << 4));
    const uint32_t b_off = (uint32_t)(((lane & 7) + ((lane >> 4) << 3)) * LDA_B
                                      + (((lane >> 3) & 1) << 4));
    const uint32_t pa = sb + K1_AHI + (uint32_t)(wm * 32 * LDA_B) + a_off;
    const uint32_t pb = sb + K1_WHI + (uint32_t)(wn * 32 * LDA_B) + b_off;

    float acc[2][4][4];
    #pragma unroll
    for (int mf = 0; mf < 2; ++mf)
        #pragma unroll
        for (int nf = 0; nf < 4; ++nf)
            #pragma unroll
            for (int v = 0; v < 4; ++v) acc[mf][nf][v] = 0.f;

    #pragma unroll
    for (int ks = 0; ks < 4; ++ks) {
        uint32_t ah[2][4], al[2][4], bh[2][4], blo[2][4];
        #pragma unroll
        for (int mf = 0; mf < 2; ++mf) {
            const uint32_t ao = pa + (uint32_t)(mf * 16 * LDA_B + ks * 32);
            LDSM4(ah[mf], ao);
            LDSM4(al[mf], ao + TILE_B);
        }
        LDSM4(bh[0],  pb + (uint32_t)(ks * 32));
        LDSM4(bh[1],  pb + (uint32_t)(16 * LDA_B + ks * 32));
        LDSM4(blo[0], pb + (uint32_t)(TILE_B + ks * 32));
        LDSM4(blo[1], pb + (uint32_t)(TILE_B + 16 * LDA_B + ks * 32));
        #pragma unroll
        for (int mf = 0; mf < 2; ++mf)
            #pragma unroll
            for (int nf = 0; nf < 4; ++nf) {
                const uint32_t b0h = bh[nf >> 1][(nf & 1) * 2];
                const uint32_t b1h = bh[nf >> 1][(nf & 1) * 2 + 1];
                MMA_BF16(acc[mf][nf], ah[mf], b0h, b1h);
                MMA_BF16(acc[mf][nf], al[mf], b0h, b1h);
                MMA_BF16(acc[mf][nf], ah[mf],
                         blo[nf >> 1][(nf & 1) * 2],
                         blo[nf >> 1][(nf & 1) * 2 + 1]);
            }
    }

    const int col0 = wn * 32 + 2 * (lane & 3);
    const int r0 = n0 + wm * 32 + (lane >> 2);
    #pragma unroll
    for (int mf = 0; mf < 2; ++mf) {
        const int ra  = r0 + mf * 16;
        const int rbw = ra + 8;
        #pragma unroll
        for (int nf = 0; nf < 4; ++nf) {
            const int c = col0 + nf * 8;
            const float b0 = bias[c], b1 = bias[c + 1];
            if (ra < N) {
                float2 v = make_float2(acc[mf][nf][0] + b0, acc[mf][nf][1] + b1);
                *(float2*)(U_buf + (size_t)ra * 128 + c) = v;
            }
            if (rbw < N) {
                float2 v = make_float2(acc[mf][nf][2] + b0, acc[mf][nf][3] + b1);
                *(float2*)(U_buf + (size_t)rbw * 128 + c) = v;
            }
        }
    }
}

// ---------------------------------------------------------------------------
// Kernel 2: out[e, :] = relu(ea[e, :] @ W2^T + U[row[e], :])
// NT=256, 8 warps (2m x 4n), B fragments persistent in registers.
// ---------------------------------------------------------------------------
__global__ void __launch_bounds__(NT2, 1)
edge_enc_kernel(const float* __restrict__ ea,
                const void*  __restrict__ eidx_raw,
                const float* __restrict__ W,
                float* __restrict__ out,
                int E)
{
    extern __shared__ __align__(1024) char smem[];
    const int tid  = threadIdx.x;
    const int lane = tid & 31;
    const int wid  = tid >> 5;      // 0..7
    const uint32_t sb = smem_u32(smem);
    float* stg  = (float*)(smem + K2_ACC);
    float* ustg = (float*)(smem + K2_UST);

    // index dtype sniff: int64 entries (values < 50000) have zero high words
    const int* e32 = (const int*)eidx_raw;
    const long long* e64 = (const long long*)eidx_raw;
    const bool is64 = ((e32[1] | e32[3] | e32[5] | e32[7]) == 0);

    const int r0s = tid >> 1;        // staging row 0..127
    const int kb  = (tid & 1) << 5;  // k-base 0 or 32

    // ---- stage W2 into the A region, load B fragments into registers -------
    {
        const float4* s = (const float4*)(W + r0s * 128 + 64 + kb);
        float4 v[8];
        #pragma unroll
        for (int j = 0; j < 8; ++j) v[j] = s[j];
        #pragma unroll
        for (int j = 0; j < 4; ++j)
            store_row8(smem, 0, r0s, kb + j * 8, v[2 * j], v[2 * j + 1]);
    }
    __syncthreads();

    const int wm = wid & 1;          // m-half: rows wm*64..+63
    const int wn = wid >> 1;         // n-quarter: cols wn*32..+31
    const uint32_t a_off = (uint32_t)((lane & 15) * LDA_B + ((lane >> 4) << 4));
    const uint32_t b_off = (uint32_t)(((lane & 7) + ((lane >> 4) << 3)) * LDA_B
                                      + (((lane >> 3) & 1) << 4));

    uint32_t Bh[4][2][4], Bl[4][2][4];
    {
        const uint32_t pbW = sb + (uint32_t)(wn * 32 * LDA_B) + b_off;
        #pragma unroll
        for (int ks = 0; ks < 4; ++ks) {
            LDSM4(Bh[ks][0], pbW + (uint32_t)(ks * 32));
            LDSM4(Bh[ks][1], pbW + (uint32_t)(16 * LDA_B + ks * 32));
            LDSM4(Bl[ks][0], pbW + (uint32_t)(TILE_B + ks * 32));
            LDSM4(Bl[ks][1], pbW + (uint32_t)(TILE_B + 16 * LDA_B + ks * 32));
        }
    }
    __syncthreads();   // everyone done reading W before A overwrites region

    const uint32_t paW = sb + (uint32_t)(wm * 64 * LDA_B) + a_off;
    const int col0 = wn * 32 + 2 * (lane & 3);
    const int wr0 = wid << 4;        // epilogue/gather: warp owns 16 rows
    const int ntiles = (E + 127) >> 7;

    // prefetch first tile (edge_attr; 32 floats/thread)
    float4 va[8];
    if (blockIdx.x < ntiles) {
        const int e = (blockIdx.x << 7) + r0s;
        if (e < E) {
            const float4* s = (const float4*)(ea + ((size_t)e << 6) + kb);
            #pragma unroll
            for (int j = 0; j < 8; ++j) va[j] = s[j];
        } else {
            #pragma unroll
            for (int j = 0; j < 8; ++j) va[j] = make_float4(0.f, 0.f, 0.f, 0.f);
        }
    }

    for (int t = blockIdx.x; t < ntiles; t += gridDim.x) {
        const int e0 = t << 7;

        // ---- stage A(t) from prefetch regs ----------------------------------
        #pragma unroll
        for (int j = 0; j < 4; ++j)
            store_row8(smem, 0, r0s, kb + j * 8, va[2 * j], va[2 * j + 1]);
        __syncthreads();   // sync1: A visible; prev acc-stage fully consumed

        // ---- cp.async gather of U rows (warp-private; hidden under MMA) -----
        {
            #pragma unroll
            for (int i = 0; i < 16; ++i) {
                const int e = e0 + wr0 + i;
                long long ri = 0;
                if (e < E) ri = is64 ? e64[e] : (long long)e32[e];
                const char* src = (const char*)(U_buf + ((size_t)ri << 7)) + (lane << 4);
                const uint32_t dst = sb + (uint32_t)(K2_UST + (wr0 + i) * 512 + (lane << 4));
                CP_ASYNC16(dst, src);
            }
            asm volatile("cp.async.commit_group;" ::: "memory");
        }

        // ---- prefetch next tile's edge_attr ---------------------------------
        const int tn = t + gridDim.x;
        if (tn < ntiles) {
            const int e = (tn << 7) + r0s;
            if (e < E) {
                const float4* s = (const float4*)(ea + ((size_t)e << 6) + kb);
                #pragma unroll
                for (int j = 0; j < 8; ++j) va[j] = s[j];
            } else {
                #pragma unroll
                for (int j = 0; j < 8; ++j) va[j] = make_float4(0.f, 0.f, 0.f, 0.f);
            }
        }

        // ---- MMA over K=64: D = Ah*Wh^T + Al*Wh^T + Ah*Wl^T (B in regs) -----
        float acc[4][4][4];
        #pragma unroll
        for (int mf = 0; mf < 4; ++mf)
            #pragma unroll
            for (int nf = 0; nf < 4; ++nf)
                #pragma unroll
                for (int v = 0; v < 4; ++v) acc[mf][nf][v] = 0.f;

        #pragma unroll
        for (int ks = 0; ks < 4; ++ks) {
            uint32_t ah[4][4], al[4][4];
            #pragma unroll
            for (int mf = 0; mf < 4; ++mf) {
                const uint32_t ao = paW + (uint32_t)(mf * 16 * LDA_B + ks * 32);
                LDSM4(ah[mf], ao);
                LDSM4(al[mf], ao + TILE_B);
            }
            // pass-major groups: 16 independent MMAs between same-acc touches
            #pragma unroll
            for (int nf = 0; nf < 4; ++nf)
                #pragma unroll
                for (int mf = 0; mf < 4; ++mf)
                    MMA_BF16(acc[mf][nf], ah[mf],
                             Bh[ks][nf >> 1][(nf & 1) * 2],
                             Bh[ks][nf >> 1][(nf & 1) * 2 + 1]);
            #pragma unroll
            for (int nf = 0; nf < 4; ++nf)
                #pragma unroll
                for (int mf = 0; mf < 4; ++mf)
                    MMA_BF16(acc[mf][nf], al[mf],
                             Bh[ks][nf >> 1][(nf & 1) * 2],
                             Bh[ks][nf >> 1][(nf & 1) * 2 + 1]);
            #pragma unroll
            for (int nf = 0; nf < 4; ++nf)
                #pragma unroll
                for (int mf = 0; mf < 4; ++mf)
                    MMA_BF16(acc[mf][nf], ah[mf],
                             Bl[ks][nf >> 1][(nf & 1) * 2],
                             Bl[ks][nf >> 1][(nf & 1) * 2 + 1]);
        }

        // ---- dump acc fragments to fp32 staging tile -------------------------
        {
            const int rl0 = wm * 64 + (lane >> 2);
            #pragma unroll
            for (int mf = 0; mf < 4; ++mf) {
                float* r0p = stg + (rl0 + mf * 16) * LDA_OUT;
                float* r1p = r0p + 8 * LDA_OUT;
                #pragma unroll
                for (int nf = 0; nf < 4; ++nf) {
                    const int c = col0 + nf * 8;
                    *(float2*)(r0p + c) = make_float2(acc[mf][nf][0], acc[mf][nf][1]);
                    *(float2*)(r1p + c) = make_float2(acc[mf][nf][2], acc[mf][nf][3]);
                }
            }
        }
        asm volatile("cp.async.wait_group 0;" ::: "memory");
        __syncthreads();   // sync2: acc-stage + all U rows visible

        // ---- coalesced epilogue: warp w owns rows 16w..16w+15 ----------------
        #pragma unroll
        for (int i = 0; i < 16; ++i) {
            const int e = e0 + wr0 + i;
            if (e < E) {
                float4 a = *(const float4*)(stg  + (wr0 + i) * LDA_OUT + (lane << 2));
                float4 u = *(const float4*)(ustg + ((wr0 + i) << 7)    + (lane << 2));
                float4 v;
                v.x = fmaxf(a.x + u.x, 0.f);
                v.y = fmaxf(a.y + u.y, 0.f);
                v.z = fmaxf(a.z + u.z, 0.f);
                v.w = fmaxf(a.w + u.w, 0.f);
                *(float4*)(out + ((size_t)e << 7) + (lane << 2)) = v;
            }
        }
        // next iteration: storeA is safe (all LDSMs precede sync2); acc-stage
        // rewrite waits for sync1; U rows are warp-private.
    }
}

extern "C" void kernel_launch(void* const* d_in, const int* in_sizes, int n_in,
                              void* d_out, int out_size) {
    const float* x  = (const float*)d_in[0];
    const float* ea = (const float*)d_in[1];
    const void*  ei = (const void*)d_in[2];
    const float* W  = (const float*)d_in[3];
    const float* b  = (const float*)d_in[4];
    float* out = (float*)d_out;

    const int N = in_sizes[0] / 64;   // x is [N, 64]
    const int E = in_sizes[1] / 64;   // edge_attr is [E, 64]
    if (E <= 0 || N <= 0) return;

    cudaFuncSetAttribute(build_u_kernel,
                         cudaFuncAttributeMaxDynamicSharedMemorySize, K1_SMEM);
    cudaFuncSetAttribute(edge_enc_kernel,
                         cudaFuncAttributeMaxDynamicSharedMemorySize, K2_SMEM);

    build_u_kernel<<<(N + 127) / 128, NT1, K1_SMEM>>>(x, W, b, N);
    edge_enc_kernel<<<148, NT2, K2_SMEM>>>(ea, ei, W, out, E);
}

// round 17
// speedup vs baseline: 1.1856x; 1.1856x over previous
#include <cuda_runtime.h>
#include <cstdint>

// ---------------------------------------------------------------------------
// DirectedEdgeEncoder: out[E,128] = relu(concat(x[row[e]], edge_attr[e]) @ W^T + b)
// Split: U = x @ W1^T + b  (N=50k rows, tiny GEMM, L2-resident scratch)
//        out[e] = relu(ea[e] @ W2^T + U[row[e]])
// mma.sync m16n8k16 bf16, fp32 accum, 3-term hi/lo split (drops lo*lo, ~1e-5).
// Kernel2: NT=512 (16 warps, 4m x 4n), SINGLE A buffer (sync2 makes it safe),
// U rows gathered via cp.async overlapped with the MMA phase, pass-major MMA
// ordering, coalesced smem-staged epilogue.
// ---------------------------------------------------------------------------

#define NT 512
#define LDA_B 144                 // bytes per bf16 tile row (64 bf16 = 128B + 16 pad)
#define TILE_B (128 * LDA_B)      // 18432 B per operand tile (128 rows x 64 k)
#define LDA_OUT 136               // fp32 acc staging pitch (floats)

// kernel-2 smem: A (hi+lo) + W2 (hi+lo) + fp32 acc staging + U staging
#define K2_AHI  0
#define K2_WHI  (2 * TILE_B)                     // 36864
#define K2_ACC  (4 * TILE_B)                     // 73728
#define K2_UST  (K2_ACC + 128 * LDA_OUT * 4)     // 73728 + 69632 = 143360
#define K2_SMEM (K2_UST + 128 * 512)             // + 65536 = 208896 B
// kernel-1 smem: single A (hi+lo) + W1 (hi+lo)
#define K1_AHI 0
#define K1_WHI (2 * TILE_B)
#define K1_SMEM (4 * TILE_B)      // 73728 B

#define U_MAX_ROWS 65536
__device__ float U_buf[(size_t)U_MAX_ROWS * 128];

static __device__ __forceinline__ uint32_t smem_u32(const void* p) {
    uint32_t a;
    asm("{ .reg .u64 t; cvta.to.shared.u64 t, %1; cvt.u32.u64 %0, t; }"
        : "=r"(a) : "l"(p));
    return a;
}

// pack two f32 -> bf16x2 (RN): 'e' low half (even k), 'o' high half (odd k)
static __device__ __forceinline__ uint32_t pack_bf16x2(float e, float o) {
    uint32_t r;
    asm("cvt.rn.bf16x2.f32 %0, %1, %2;" : "=r"(r) : "f"(o), "f"(e));
    return r;
}

// split (e,o) into bf16 hi word + bf16 lo (residual) word
static __device__ __forceinline__ void cvt2(float e, float o,
                                            uint32_t& hw, uint32_t& lw) {
    hw = pack_bf16x2(e, o);
    float fe = __uint_as_float(hw << 16);
    float fo = __uint_as_float(hw & 0xFFFF0000u);
    lw = pack_bf16x2(e - fe, o - fo);
}

#define LDSM4(r, addr)                                                        \
    asm volatile("ldmatrix.sync.aligned.m8n8.x4.shared.b16 {%0,%1,%2,%3}, [%4];" \
                 : "=r"((r)[0]), "=r"((r)[1]), "=r"((r)[2]), "=r"((r)[3])     \
                 : "r"(addr))

#define MMA_BF16(d, a, b0, b1)                                                \
    asm volatile("mma.sync.aligned.m16n8k16.row.col.f32.bf16.bf16.f32 "       \
                 "{%0,%1,%2,%3}, {%4,%5,%6,%7}, {%8,%9}, {%0,%1,%2,%3};"      \
                 : "+f"((d)[0]), "+f"((d)[1]), "+f"((d)[2]), "+f"((d)[3])     \
                 : "r"((a)[0]), "r"((a)[1]), "r"((a)[2]), "r"((a)[3]),        \
                   "r"(b0), "r"(b1))

#define CP_ASYNC16(dst, src)                                                  \
    asm volatile("cp.async.cg.shared.global [%0], [%1], 16;"                  \
                 :: "r"(dst), "l"(src) : "memory")

// convert 2 float4 (8 consecutive k-values of one row) -> bf16 hi/lo in SMEM
static __device__ __forceinline__ void store_row8(char* smem, int hi_off,
                                                  int r, int k0,
                                                  float4 a, float4 b) {
    uint32_t h[4], l[4];
    cvt2(a.x, a.y, h[0], l[0]);
    cvt2(a.z, a.w, h[1], l[1]);
    cvt2(b.x, b.y, h[2], l[2]);
    cvt2(b.z, b.w, h[3], l[3]);
    int off = r * LDA_B + (k0 << 1);
    *(uint4*)(smem + hi_off + off) = make_uint4(h[0], h[1], h[2], h[3]);
    *(uint4*)(smem + hi_off + TILE_B + off) = make_uint4(l[0], l[1], l[2], l[3]);
}

// NT-wide: stage a [128 x 64] fp32 W slice (row stride 128 fl) as bf16 hi/lo
static __device__ __forceinline__ void stage_w(char* smem, int hi_off,
                                               const float* __restrict__ Wsl,
                                               int tid) {
    const int g = tid & 7, k0 = g << 3;
    const int r0 = tid >> 3;           // 0..63
    #pragma unroll
    for (int i = 0; i < 2; ++i) {
        int r = r0 + (i << 6);
        const float4* s = (const float4*)(Wsl + r * 128 + k0);
        store_row8(smem, hi_off, r, k0, s[0], s[1]);
    }
}

// ---------------------------------------------------------------------------
// Kernel 1: U[n, :] = x[n, :] @ W1^T + b     (no relu), n in [0, N)
// ---------------------------------------------------------------------------
__global__ void __launch_bounds__(NT, 1)
build_u_kernel(const float* __restrict__ x,
               const float* __restrict__ W,
               const float* __restrict__ bias,
               int N)
{
    extern __shared__ __align__(1024) char smem[];
    const int tid  = threadIdx.x;
    const int lane = tid & 31;
    const int wid  = tid >> 5;
    const uint32_t sb = smem_u32(smem);
    const int n0 = blockIdx.x << 7;

    stage_w(smem, K1_WHI, W, tid);     // W1 = W[:, 0:64]

    // A tile: x rows n0..n0+127 (K = 64)
    {
        const int g = tid & 7, k0 = g << 3;
        const int r0 = tid >> 3;
        #pragma unroll
        for (int i = 0; i < 2; ++i) {
            int r = r0 + (i << 6);
            float4 a, b;
            if (n0 + r < N) {
                const float4* s = (const float4*)(x + ((size_t)(n0 + r) << 6) + k0);
                a = s[0]; b = s[1];
            } else {
                a = make_float4(0.f, 0.f, 0.f, 0.f); b = a;
            }
            store_row8(smem, K1_AHI, r, k0, a, b);
        }
    }
    __syncthreads();

    const int wm = wid & 3;
    const int wn = wid >> 2;
    const uint32_t a_off = (uint32_t)((lane & 15) * LDA_B + ((lane >> 4) << 4));
    const uint32_t b_off = (uint32_t)(((lane & 7) + ((lane >> 4) << 3)) * LDA_B
                                      + (((lane >> 3) & 1) << 4));
    const uint32_t pa = sb + K1_AHI + (uint32_t)(wm * 32 * LDA_B) + a_off;
    const uint32_t pb = sb + K1_WHI + (uint32_t)(wn * 32 * LDA_B) + b_off;

    float acc[2][4][4];
    #pragma unroll
    for (int mf = 0; mf < 2; ++mf)
        #pragma unroll
        for (int nf = 0; nf < 4; ++nf)
            #pragma unroll
            for (int v = 0; v < 4; ++v) acc[mf][nf][v] = 0.f;

    #pragma unroll
    for (int ks = 0; ks < 4; ++ks) {
        uint32_t ah[2][4], al[2][4], bh[2][4], blo[2][4];
        #pragma unroll
        for (int mf = 0; mf < 2; ++mf) {
            const uint32_t ao = pa + (uint32_t)(mf * 16 * LDA_B + ks * 32);
            LDSM4(ah[mf], ao);
            LDSM4(al[mf], ao + TILE_B);
        }
        LDSM4(bh[0],  pb + (uint32_t)(ks * 32));
        LDSM4(bh[1],  pb + (uint32_t)(16 * LDA_B + ks * 32));
        LDSM4(blo[0], pb + (uint32_t)(TILE_B + ks * 32));
        LDSM4(blo[1], pb + (uint32_t)(TILE_B + 16 * LDA_B + ks * 32));
        #pragma unroll
        for (int nf = 0; nf < 4; ++nf)
            #pragma unroll
            for (int mf = 0; mf < 2; ++mf)
                MMA_BF16(acc[mf][nf], ah[mf],
                         bh[nf >> 1][(nf & 1) * 2], bh[nf >> 1][(nf & 1) * 2 + 1]);
        #pragma unroll
        for (int nf = 0; nf < 4; ++nf)
            #pragma unroll
            for (int mf = 0; mf < 2; ++mf)
                MMA_BF16(acc[mf][nf], al[mf],
                         bh[nf >> 1][(nf & 1) * 2], bh[nf >> 1][(nf & 1) * 2 + 1]);
        #pragma unroll
        for (int nf = 0; nf < 4; ++nf)
            #pragma unroll
            for (int mf = 0; mf < 2; ++mf)
                MMA_BF16(acc[mf][nf], ah[mf],
                         blo[nf >> 1][(nf & 1) * 2], blo[nf >> 1][(nf & 1) * 2 + 1]);
    }

    const int col0 = wn * 32 + 2 * (lane & 3);
    const int r0 = n0 + wm * 32 + (lane >> 2);
    #pragma unroll
    for (int mf = 0; mf < 2; ++mf) {
        const int ra  = r0 + mf * 16;
        const int rbw = ra + 8;
        #pragma unroll
        for (int nf = 0; nf < 4; ++nf) {
            const int c = col0 + nf * 8;
            const float b0 = bias[c], b1 = bias[c + 1];
            if (ra < N) {
                float2 v = make_float2(acc[mf][nf][0] + b0, acc[mf][nf][1] + b1);
                *(float2*)(U_buf + (size_t)ra * 128 + c) = v;
            }
            if (rbw < N) {
                float2 v = make_float2(acc[mf][nf][2] + b0, acc[mf][nf][3] + b1);
                *(float2*)(U_buf + (size_t)rbw * 128 + c) = v;
            }
        }
    }
}

// ---------------------------------------------------------------------------
// Kernel 2: out[e, :] = relu(ea[e, :] @ W2^T + U[row[e], :])
// ---------------------------------------------------------------------------
__global__ void __launch_bounds__(NT, 1)
edge_enc_kernel(const float* __restrict__ ea,
                const void*  __restrict__ eidx_raw,
                const float* __restrict__ W,
                float* __restrict__ out,
                int E)
{
    extern __shared__ __align__(1024) char smem[];
    const int tid  = threadIdx.x;
    const int lane = tid & 31;
    const int wid  = tid >> 5;      // 0..15
    const uint32_t sb = smem_u32(smem);
    float* stg  = (float*)(smem + K2_ACC);
    float* ustg = (float*)(smem + K2_UST);

    // index dtype sniff: int64 entries (values < 50000) have zero high words
    const int* e32 = (const int*)eidx_raw;
    const long long* e64 = (const long long*)eidx_raw;
    const bool is64 = ((e32[1] | e32[3] | e32[5] | e32[7]) == 0);

    stage_w(smem, K2_WHI, W + 64, tid);   // W2 = W[:, 64:128]

    const int g  = tid & 7, k0 = g << 3;
    const int r0s = tid >> 3;             // staging row base 0..63

    const int wm = wid & 3;
    const int wn = wid >> 2;
    const uint32_t a_off = (uint32_t)((lane & 15) * LDA_B + ((lane >> 4) << 4));
    const uint32_t b_off = (uint32_t)(((lane & 7) + ((lane >> 4) << 3)) * LDA_B
                                      + (((lane >> 3) & 1) << 4));
    const uint32_t pa = sb + K2_AHI + (uint32_t)(wm * 32 * LDA_B) + a_off;
    const uint32_t pb = sb + K2_WHI + (uint32_t)(wn * 32 * LDA_B) + b_off;

    const int col0 = wn * 32 + 2 * (lane & 3);
    const int wr0 = wid << 3;        // epilogue/gather: warp owns 8 rows
    const int ntiles = (E + 127) >> 7;

    // prefetch first tile (edge_attr; 16 floats/thread)
    float4 va[2], vb[2];
    if (blockIdx.x < ntiles) {
        const int e0 = blockIdx.x << 7;
        #pragma unroll
        for (int i = 0; i < 2; ++i) {
            int e = e0 + r0s + (i << 6);
            if (e < E) {
                const float4* s = (const float4*)(ea + ((size_t)e << 6) + k0);
                va[i] = s[0]; vb[i] = s[1];
            } else {
                va[i] = make_float4(0.f, 0.f, 0.f, 0.f); vb[i] = va[i];
            }
        }
    }

    for (int t = blockIdx.x; t < ntiles; t += gridDim.x) {
        const int e0 = t << 7;

        // ---- stage A(t). Safe with a single buffer: every warp past sync2 of
        // tile t-1 has observed ALL warps' LDSMs of A(t-1) complete.
        #pragma unroll
        for (int i = 0; i < 2; ++i)
            store_row8(smem, K2_AHI, r0s + (i << 6), k0, va[i], vb[i]);
        __syncthreads();   // sync1

        // ---- cp.async gather of U rows (warp-private; hidden under MMA) -----
        {
            #pragma unroll
            for (int i = 0; i < 8; ++i) {
                const int e = e0 + wr0 + i;
                long long ri = 0;
                if (e < E) ri = is64 ? e64[e] : (long long)e32[e];
                const char* src = (const char*)(U_buf + ((size_t)ri << 7)) + (lane << 4);
                const uint32_t dst = sb + (uint32_t)(K2_UST + (wr0 + i) * 512 + (lane << 4));
                CP_ASYNC16(dst, src);
            }
            asm volatile("cp.async.commit_group;" ::: "memory");
        }

        // ---- prefetch next tile's edge_attr ---------------------------------
        const int tn = t + gridDim.x;
        if (tn < ntiles) {
            const int en = tn << 7;
            #pragma unroll
            for (int i = 0; i < 2; ++i) {
                int e = en + r0s + (i << 6);
                if (e < E) {
                    const float4* s = (const float4*)(ea + ((size_t)e << 6) + k0);
                    va[i] = s[0]; vb[i] = s[1];
                } else {
                    va[i] = make_float4(0.f, 0.f, 0.f, 0.f); vb[i] = va[i];
                }
            }
        }

        // ---- MMA over K=64: D = Ah*Wh^T + Al*Wh^T + Ah*Wl^T -----------------
        float acc[2][4][4];
        #pragma unroll
        for (int mf = 0; mf < 2; ++mf)
            #pragma unroll
            for (int nf = 0; nf < 4; ++nf)
                #pragma unroll
                for (int v = 0; v < 4; ++v) acc[mf][nf][v] = 0.f;

        #pragma unroll
        for (int ks = 0; ks < 4; ++ks) {
            uint32_t ah[2][4], al[2][4], bh[2][4], blo[2][4];
            #pragma unroll
            for (int mf = 0; mf < 2; ++mf) {
                const uint32_t ao = pa + (uint32_t)(mf * 16 * LDA_B + ks * 32);
                LDSM4(ah[mf], ao);
                LDSM4(al[mf], ao + TILE_B);
            }
            LDSM4(bh[0],  pb + (uint32_t)(ks * 32));
            LDSM4(bh[1],  pb + (uint32_t)(16 * LDA_B + ks * 32));
            LDSM4(blo[0], pb + (uint32_t)(TILE_B + ks * 32));
            LDSM4(blo[1], pb + (uint32_t)(TILE_B + 16 * LDA_B + ks * 32));
            // pass-major: 8 independent MMAs between same-acc touches
            #pragma unroll
            for (int nf = 0; nf < 4; ++nf)
                #pragma unroll
                for (int mf = 0; mf < 2; ++mf)
                    MMA_BF16(acc[mf][nf], ah[mf],
                             bh[nf >> 1][(nf & 1) * 2], bh[nf >> 1][(nf & 1) * 2 + 1]);
            #pragma unroll
            for (int nf = 0; nf < 4; ++nf)
                #pragma unroll
                for (int mf = 0; mf < 2; ++mf)
                    MMA_BF16(acc[mf][nf], al[mf],
                             bh[nf >> 1][(nf & 1) * 2], bh[nf >> 1][(nf & 1) * 2 + 1]);
            #pragma unroll
            for (int nf = 0; nf < 4; ++nf)
                #pragma unroll
                for (int mf = 0; mf < 2; ++mf)
                    MMA_BF16(acc[mf][nf], ah[mf],
                             blo[nf >> 1][(nf & 1) * 2], blo[nf >> 1][(nf & 1) * 2 + 1]);
        }

        // ---- dump acc fragments to fp32 staging tile -------------------------
        {
            const int rl0 = wm * 32 + (lane >> 2);
            #pragma unroll
            for (int mf = 0; mf < 2; ++mf) {
                float* r0p = stg + (rl0 + mf * 16) * LDA_OUT;
                float* r1p = r0p + 8 * LDA_OUT;
                #pragma unroll
                for (int nf = 0; nf < 4; ++nf) {
                    const int c = col0 + nf * 8;
                    *(float2*)(r0p + c) = make_float2(acc[mf][nf][0], acc[mf][nf][1]);
                    *(float2*)(r1p + c) = make_float2(acc[mf][nf][2], acc[mf][nf][3]);
                }
            }
        }
        asm volatile("cp.async.wait_group 0;" ::: "memory");
        __syncthreads();   // sync2: acc staging + U rows visible to all

        // ---- coalesced epilogue: warp w owns rows 8w..8w+7 -------------------
        #pragma unroll
        for (int i = 0; i < 8; ++i) {
            const int e = e0 + wr0 + i;
            if (e < E) {
                float4 a = *(const float4*)(stg  + (wr0 + i) * LDA_OUT + (lane << 2));
                float4 u = *(const float4*)(ustg + ((wr0 + i) << 7)    + (lane << 2));
                float4 v;
                v.x = fmaxf(a.x + u.x, 0.f);
                v.y = fmaxf(a.y + u.y, 0.f);
                v.z = fmaxf(a.z + u.z, 0.f);
                v.w = fmaxf(a.w + u.w, 0.f);
                *(float4*)(out + ((size_t)e << 7) + (lane << 2)) = v;
            }
        }
    }
}

extern "C" void kernel_launch(void* const* d_in, const int* in_sizes, int n_in,
                              void* d_out, int out_size) {
    const float* x  = (const float*)d_in[0];
    const float* ea = (const float*)d_in[1];
    const void*  ei = (const void*)d_in[2];
    const float* W  = (const float*)d_in[3];
    const float* b  = (const float*)d_in[4];
    float* out = (float*)d_out;

    const int N = in_sizes[0] / 64;   // x is [N, 64]
    const int E = in_sizes[1] / 64;   // edge_attr is [E, 64]
    if (E <= 0 || N <= 0) return;

    cudaFuncSetAttribute(build_u_kernel,
                         cudaFuncAttributeMaxDynamicSharedMemorySize, K1_SMEM);
    cudaFuncSetAttribute(edge_enc_kernel,
                         cudaFuncAttributeMaxDynamicSharedMemorySize, K2_SMEM);

    build_u_kernel<<<(N + 127) / 128, NT, K1_SMEM>>>(x, W, b, N);
    edge_enc_kernel<<<148, NT, K2_SMEM>>>(ea, ei, W, out, E);
}